// round 15
// baseline (speedup 1.0000x reference)
#include <cuda_runtime.h>
#include <cuda_bf16.h>
#include <math.h>

// Problem constants
#define BB 4
#define NN 2048
#define CC 192
#define HH 6
#define DD 32
#define KK 16
#define CH 96          // offset hidden
#define PH 48          // pos hidden
#define ROWS (BB*NN)   // 8192
#define QKVN (3*CC)    // 576

// ---------------- scratch (static device globals; no allocation) ----------------
__device__ float  g_qkv[ROWS * QKVN];      // 18.9 MB
__device__ float  g_h1[ROWS * CH];         // 3.1 MB
__device__ float  g_off[ROWS * 3 * KK];    // 1.57 MB  [B,N,K,3]
__device__ int    g_nn[ROWS * KK];         // nearest indices
__device__ float  g_attn_out[ROWS * CC];   // 6.3 MB
// grid acceleration structure (8x8x8 cells per batch)
__device__ float4 g_ckeys[BB * NN];        // cell-sorted packed keys (x,y,z,S)
__device__ int    g_cidx[BB * NN];         // original key index per sorted slot
__device__ int    g_cstart[BB * 513];      // cell start offsets (exclusive scan)

// ---------------- XLA/Eigen-replica erf (f32 rational, clamp [-4,4]) ------------
__device__ __forceinline__ float xla_erf(float x) {
    x = fmaxf(fminf(x, 4.0f), -4.0f);
    float x2 = __fmul_rn(x, x);
    float p = -2.72614225801306e-10f;
    p = __fmaf_rn(p, x2,  2.77068142495902e-08f);
    p = __fmaf_rn(p, x2, -2.10102402082508e-06f);
    p = __fmaf_rn(p, x2, -5.69250639462346e-05f);
    p = __fmaf_rn(p, x2, -7.34990630326855e-04f);
    p = __fmaf_rn(p, x2, -2.95459980854025e-03f);
    p = __fmaf_rn(p, x2, -1.60960333262415e-02f);
    p = __fmul_rn(x, p);
    float q = -1.45660718464996e-05f;
    q = __fmaf_rn(q, x2, -2.13374055278905e-04f);
    q = __fmaf_rn(q, x2, -1.68282697438203e-03f);
    q = __fmaf_rn(q, x2, -7.37332916720468e-03f);
    q = __fmaf_rn(q, x2, -1.42647390514189e-02f);
    return __fdiv_rn(p, q);
}

// jax.nn.gelu(approximate=False) bit-exact replica
__device__ __forceinline__ float gelu_ref(float x) {
    float t = __fdiv_rn(x, 1.41421356237309504880f);
    float e = xla_erf(t);
    return __fmul_rn(__fmul_rn(x, __fadd_rn(e, 1.0f)), 0.5f);
}

// ---------------- GEMM v2: BM=128, BN=64, BK=16, 256 thr, 8x4 microtile ---------
template<bool GELU>
__global__ void gemm128_kernel(const float* __restrict__ A, const float* __restrict__ B,
                               const float* __restrict__ bias, float* __restrict__ C,
                               int N, int K) {
    __shared__ float As[16][132];
    __shared__ float Bs[16][64];
    const int tid = threadIdx.x;
    const int tx = tid & 15;
    const int ty = tid >> 4;
    const int rowBase = blockIdx.y * 128;
    const int colBase = blockIdx.x * 64;

    float acc[8][4];
#pragma unroll
    for (int i = 0; i < 8; i++)
#pragma unroll
        for (int j = 0; j < 4; j++) acc[i][j] = 0.f;

    for (int k0 = 0; k0 < K; k0 += 16) {
#pragma unroll
        for (int t = 0; t < 8; t++) {
            int idx = tid + t * 256;
            int r = idx >> 4, c = idx & 15;
            As[c][r] = A[(rowBase + r) * K + k0 + c];
        }
#pragma unroll
        for (int t = 0; t < 4; t++) {
            int idx = tid + t * 256;
            int r = idx >> 6, c = idx & 63;
            int col = colBase + c;
            Bs[r][c] = (col < N) ? B[(k0 + r) * N + col] : 0.f;
        }
        __syncthreads();
#pragma unroll
        for (int k = 0; k < 16; k++) {
            float4 a0 = *(const float4*)&As[k][ty * 8];
            float4 a1 = *(const float4*)&As[k][ty * 8 + 4];
            float4 bv4 = *(const float4*)&Bs[k][tx * 4];
            float av[8] = {a0.x, a0.y, a0.z, a0.w, a1.x, a1.y, a1.z, a1.w};
            float bv[4] = {bv4.x, bv4.y, bv4.z, bv4.w};
#pragma unroll
            for (int i = 0; i < 8; i++)
#pragma unroll
                for (int j = 0; j < 4; j++)
                    acc[i][j] = __fmaf_rn(av[i], bv[j], acc[i][j]);
        }
        __syncthreads();
    }
#pragma unroll
    for (int i = 0; i < 8; i++) {
        int row = rowBase + ty * 8 + i;
#pragma unroll
        for (int j = 0; j < 4; j++) {
            int col = colBase + tx * 4 + j;
            if (col < N) {
                float v = __fadd_rn(acc[i][j], bias[col]);
                if (GELU) v = gelu_ref(v);
                C[row * N + col] = v;
            }
        }
    }
}

// ---------------- GEMM 64x64 (kept for the N=48 offset GEMM) -------------------
template<bool GELU>
__global__ void gemm_bias_kernel(const float* __restrict__ A, const float* __restrict__ B,
                                 const float* __restrict__ bias, float* __restrict__ C,
                                 int M, int N, int K) {
    __shared__ float As[16][68];
    __shared__ float Bs[16][64];
    const int tid = threadIdx.x;
    const int tx = tid & 15;
    const int ty = tid >> 4;
    const int rowBase = blockIdx.y * 64;
    const int colBase = blockIdx.x * 64;

    float acc[4][4];
#pragma unroll
    for (int i = 0; i < 4; i++)
#pragma unroll
        for (int j = 0; j < 4; j++) acc[i][j] = 0.f;

    for (int k0 = 0; k0 < K; k0 += 16) {
#pragma unroll
        for (int t = 0; t < 4; t++) {
            int idx = tid + t * 256;
            int r = idx >> 4, c = idx & 15;
            As[c][r] = A[(rowBase + r) * K + k0 + c];
        }
#pragma unroll
        for (int t = 0; t < 4; t++) {
            int idx = tid + t * 256;
            int r = idx >> 6, c = idx & 63;
            int col = colBase + c;
            Bs[r][c] = (col < N) ? B[(k0 + r) * N + col] : 0.f;
        }
        __syncthreads();
#pragma unroll
        for (int k = 0; k < 16; k++) {
            float4 av4 = *(const float4*)&As[k][ty * 4];
            float4 bv4 = *(const float4*)&Bs[k][tx * 4];
            float av[4] = {av4.x, av4.y, av4.z, av4.w};
            float bv[4] = {bv4.x, bv4.y, bv4.z, bv4.w};
#pragma unroll
            for (int i = 0; i < 4; i++)
#pragma unroll
                for (int j = 0; j < 4; j++)
                    acc[i][j] = __fmaf_rn(av[i], bv[j], acc[i][j]);
        }
        __syncthreads();
    }
#pragma unroll
    for (int i = 0; i < 4; i++) {
        int row = rowBase + ty * 4 + i;
#pragma unroll
        for (int j = 0; j < 4; j++) {
            int col = colBase + tx * 4 + j;
            if (col < N) {
                float v = __fadd_rn(acc[i][j], bias[col]);
                if (GELU) v = gelu_ref(v);
                C[row * N + col] = v;
            }
        }
    }
}

// ---------------- grid build: one block per batch, 8x8x8 cells ------------------
__global__ void grid_build_kernel(const float* __restrict__ coords) {
    __shared__ int cnt[512];
    __shared__ int cur[512];
    __shared__ int scanbuf[512];
    const int b = blockIdx.x;
    const int tid = threadIdx.x;
    cnt[tid] = 0;
    __syncthreads();

    int    kcell[4];
    float4 kval[4];
#pragma unroll
    for (int t = 0; t < 4; t++) {
        int i = tid + t * 512;
        const float* c = coords + (b * NN + i) * 3;
        float x = c[0], y = c[1], z = c[2];
        // packed S with the exact reference chain
        float s = __fadd_rn(__fadd_rn(__fmul_rn(x, x), __fmul_rn(y, y)), __fmul_rn(z, z));
        int cx = min(7, max(0, (int)floorf(x * 8.f)));
        int cy = min(7, max(0, (int)floorf(y * 8.f)));
        int cz = min(7, max(0, (int)floorf(z * 8.f)));
        kcell[t] = (cx * 8 + cy) * 8 + cz;
        kval[t] = make_float4(x, y, z, s);
        atomicAdd(&cnt[kcell[t]], 1);
    }
    __syncthreads();

    // inclusive scan (Hillis-Steele) of cnt
    int v = cnt[tid];
    scanbuf[tid] = v;
    __syncthreads();
    for (int off = 1; off < 512; off <<= 1) {
        int add = (tid >= off) ? scanbuf[tid - off] : 0;
        __syncthreads();
        scanbuf[tid] += add;
        __syncthreads();
    }
    int excl = scanbuf[tid] - v;
    g_cstart[b * 513 + tid] = excl;
    if (tid == 0) g_cstart[b * 513 + 512] = NN;
    cur[tid] = excl;
    __syncthreads();

#pragma unroll
    for (int t = 0; t < 4; t++) {
        int i = tid + t * 512;
        int slot = atomicAdd(&cur[kcell[t]], 1);
        g_ckeys[b * NN + slot] = kval[t];
        g_cidx[b * NN + slot] = i;
    }
}

// ---------------- nearest neighbor v5: grid-pruned exact argmin -----------------
// Every evaluated pair uses the frozen reference-exact d2 chain:
//   sp  = c + fl(10*o);  S = (sx^2+sy^2)+sz^2
//   dot = fma(sz,kz, fma(sy,ky, sx*kx));  d2 = (S - 2*dot) + C_key
// Pruning is conservative: stop only when bnd^2 - 4e-3 > best, which strictly
// excludes unvisited keys from beating OR tying best (fp error << 4e-3).
// Tie rule (d<best)||(d==best && idx<bi) == jnp.argmin first-min, order-free.
__global__ void __launch_bounds__(512, 2) nn_query_kernel(const float* __restrict__ coords) {
    __shared__ float4 sk[NN];      // 32 KB sorted keys
    __shared__ int    sidx[NN];    // 8 KB original indices
    __shared__ int    sst[513];    // cell starts
    const int b = blockIdx.y;
    for (int i = threadIdx.x; i < NN; i += 512) { sk[i] = g_ckeys[b * NN + i]; sidx[i] = g_cidx[b * NN + i]; }
    for (int i = threadIdx.x; i < 513; i += 512) sst[i] = g_cstart[b * 513 + i];
    __syncthreads();

    const int qi = blockIdx.x * 512 + threadIdx.x;   // 0..32767
    const int n = qi >> 4, k = qi & 15;
    const float* cr = coords + (b * NN + n) * 3;
    const float* of = g_off + (b * NN + n) * 48 + k * 3;
    const float sx = __fadd_rn(cr[0], __fmul_rn(of[0], 10.0f));
    const float sy = __fadd_rn(cr[1], __fmul_rn(of[1], 10.0f));
    const float sz = __fadd_rn(cr[2], __fmul_rn(of[2], 10.0f));
    const float S  = __fadd_rn(__fadd_rn(__fmul_rn(sx, sx), __fmul_rn(sy, sy)),
                               __fmul_rn(sz, sz));
    const int cx = min(7, max(0, (int)floorf(sx * 8.f)));
    const int cy = min(7, max(0, (int)floorf(sy * 8.f)));
    const int cz = min(7, max(0, (int)floorf(sz * 8.f)));

    float best = 3.4e38f;
    int   bi   = 0x7fffffff;

#define NN_EVAL(J) { \
        float4 kk = sk[J]; \
        float dot = __fmaf_rn(sz, kk.z, __fmaf_rn(sy, kk.y, __fmul_rn(sx, kk.x))); \
        float d = __fadd_rn(__fmaf_rn(dot, -2.0f, S), kk.w); \
        int idx = sidx[J]; \
        if (d < best) { best = d; bi = idx; } \
        else if (d == best && idx < bi) { bi = idx; } \
    }

    for (int r = 0; r < 8; r++) {
        for (int X = cx - r; X <= cx + r; X++) {
            if ((unsigned)X > 7u) continue;
            int adx = abs(X - cx);
            for (int Y = cy - r; Y <= cy + r; Y++) {
                if ((unsigned)Y > 7u) continue;
                int mxy = max(adx, abs(Y - cy));
                int colbase = (X * 8 + Y) * 8;
                if (mxy == r) {
                    // full z-run (contiguous cells -> one contiguous key range)
                    int z0 = max(cz - r, 0), z1 = min(cz + r, 7);
                    int s0 = sst[colbase + z0], e0 = sst[colbase + z1 + 1];
                    for (int j = s0; j < e0; j++) NN_EVAL(j)
                } else {
                    // only the two z-extremes are new at this ring
                    int zl = cz - r;
                    if (zl >= 0) {
                        int c0 = colbase + zl;
                        int s0 = sst[c0], e0 = sst[c0 + 1];
                        for (int j = s0; j < e0; j++) NN_EVAL(j)
                    }
                    int zh = cz + r;
                    if (zh <= 7) {
                        int c0 = colbase + zh;
                        int s0 = sst[c0], e0 = sst[c0 + 1];
                        for (int j = s0; j < e0; j++) NN_EVAL(j)
                    }
                }
            }
        }
        // conservative ring bound: min distance to any unvisited (outside-box) key
        float bnd = 3.4e38f;
        if (cx - r > 0) bnd = fminf(bnd, sx - (float)(cx - r) * 0.125f);
        if (cx + r < 7) bnd = fminf(bnd, (float)(cx + r + 1) * 0.125f - sx);
        if (cy - r > 0) bnd = fminf(bnd, sy - (float)(cy - r) * 0.125f);
        if (cy + r < 7) bnd = fminf(bnd, (float)(cy + r + 1) * 0.125f - sy);
        if (cz - r > 0) bnd = fminf(bnd, sz - (float)(cz - r) * 0.125f);
        if (cz + r < 7) bnd = fminf(bnd, (float)(cz + r + 1) * 0.125f - sz);
        if (bnd == 3.4e38f) break;                       // box covers whole domain
        if (__fmaf_rn(bnd, bnd, -4e-3f) > best) break;   // no unvisited key can win/tie
    }
#undef NN_EVAL

    g_nn[b * (NN * KK) + qi] = bi;
}

// ---------------- attention + pos-bias MLP (R13 version, best) ------------------
__global__ void attn_kernel(const float* __restrict__ pos_w1, const float* __restrict__ pos_b1,
                            const float* __restrict__ pos_w2, const float* __restrict__ pos_b2) {
    __shared__ float spw1[144], spb1[48], spw2[288], spb2[8];
    __shared__ float shid[8][768];
    __shared__ float sbias[8][96];
    __shared__ float soff[8][48];
    __shared__ int   snn[8][16];

    const int tid = threadIdx.x;
    for (int i = tid; i < 144; i += 256) spw1[i] = pos_w1[i];
    for (int i = tid; i < 48;  i += 256) spb1[i] = pos_b1[i];
    for (int i = tid; i < 288; i += 256) spw2[i] = pos_w2[i];
    if (tid < 6) spb2[tid] = pos_b2[tid];
    __syncthreads();

    const int w = tid >> 5, lane = tid & 31;
    const int gw = blockIdx.x * 8 + w;      // 0..8191
    const int b = gw >> 11, n = gw & 2047;
    const int row = b * NN + n;

    for (int t = lane; t < 48; t += 32) soff[w][t] = g_off[row * 48 + t];
    if (lane < 16) snn[w][lane] = g_nn[row * 16 + lane];
    __syncwarp();

#pragma unroll 4
    for (int t = 0; t < 24; t++) {
        int idx = t * 32 + lane;
        int k = idx / 48, j = idx - k * 48;
        float o0 = soff[w][k * 3 + 0];
        float o1 = soff[w][k * 3 + 1];
        float o2 = soff[w][k * 3 + 2];
        float hv = __fmaf_rn(o0, spw1[j], spb1[j]);
        hv = __fmaf_rn(o1, spw1[48 + j], hv);
        hv = __fmaf_rn(o2, spw1[96 + j], hv);
        shid[w][k * 48 + j] = gelu_ref(hv);
    }
    __syncwarp();

#pragma unroll
    for (int t = 0; t < 3; t++) {
        int idx = t * 32 + lane;
        int k = idx / 6, h = idx - k * 6;
        float s = spb2[h];
#pragma unroll 8
        for (int j = 0; j < 48; j++)
            s = __fmaf_rn(shid[w][k * 48 + j], spw2[j * 6 + h], s);
        sbias[w][idx] = s;
    }
    __syncwarp();

    const float* qrow = g_qkv + (size_t)row * QKVN;
    float* orow = g_attn_out + (size_t)row * CC;
    const unsigned FULL = 0xffffffffu;

    for (int h = 0; h < HH; h++) {
        float qd = qrow[h * DD + lane];
        float lk = 0.f;
#pragma unroll
        for (int k = 0; k < KK; k++) {
            int nk = snn[w][k];
            float kv = g_qkv[(size_t)(b * NN + nk) * QKVN + CC + h * DD + lane];
            float p = qd * kv;
            p += __shfl_xor_sync(FULL, p, 16);
            p += __shfl_xor_sync(FULL, p, 8);
            p += __shfl_xor_sync(FULL, p, 4);
            p += __shfl_xor_sync(FULL, p, 2);
            p += __shfl_xor_sync(FULL, p, 1);
            if (lane == k) lk = p;
        }
        float logit = (lane < KK)
                      ? (lk * 0.17677669529663687f + sbias[w][lane * 6 + h])
                      : -1e30f;
        float m = logit;
        m = fmaxf(m, __shfl_xor_sync(FULL, m, 8));
        m = fmaxf(m, __shfl_xor_sync(FULL, m, 4));
        m = fmaxf(m, __shfl_xor_sync(FULL, m, 2));
        m = fmaxf(m, __shfl_xor_sync(FULL, m, 1));
        float e = (lane < KK) ? expf(logit - m) : 0.f;
        float s = e;
        s += __shfl_xor_sync(FULL, s, 8);
        s += __shfl_xor_sync(FULL, s, 4);
        s += __shfl_xor_sync(FULL, s, 2);
        s += __shfl_xor_sync(FULL, s, 1);
        float a = e / s;
        float od = 0.f;
#pragma unroll
        for (int k = 0; k < KK; k++) {
            float ak = __shfl_sync(FULL, a, k);
            int nk = snn[w][k];
            float vv = g_qkv[(size_t)(b * NN + nk) * QKVN + 2 * CC + h * DD + lane];
            od = __fmaf_rn(ak, vv, od);
        }
        orow[h * DD + lane] = od;
    }
}

// ---------------- launch (forked: {build,qkv} ∥ {h1→off}; join → NN → attn) -----
extern "C" void kernel_launch(void* const* d_in, const int* in_sizes, int n_in,
                              void* d_out, int out_size) {
    const float* coords  = (const float*)d_in[0];
    const float* x       = (const float*)d_in[1];
    const float* qkv_w   = (const float*)d_in[2];
    const float* qkv_b   = (const float*)d_in[3];
    const float* proj_w  = (const float*)d_in[4];
    const float* proj_b  = (const float*)d_in[5];
    const float* off_w1  = (const float*)d_in[6];
    const float* off_b1  = (const float*)d_in[7];
    const float* off_w2  = (const float*)d_in[8];
    const float* off_b2  = (const float*)d_in[9];
    const float* pos_w1  = (const float*)d_in[10];
    const float* pos_b1  = (const float*)d_in[11];
    const float* pos_w2  = (const float*)d_in[12];
    const float* pos_b2  = (const float*)d_in[13];
    float* out = (float*)d_out;

    float *qkv_p, *h1_p, *off_p, *att_p;
    cudaGetSymbolAddress((void**)&qkv_p, g_qkv);
    cudaGetSymbolAddress((void**)&h1_p,  g_h1);
    cudaGetSymbolAddress((void**)&off_p, g_off);
    cudaGetSymbolAddress((void**)&att_p, g_attn_out);

    // Lazily-created side stream + events (host-side objects only).
    static cudaStream_t s_side = nullptr;
    static cudaEvent_t  s_fork = nullptr, s_join = nullptr, s_build = nullptr;
    if (s_side == nullptr) {
        cudaStreamCreateWithFlags(&s_side, cudaStreamNonBlocking);
        cudaEventCreateWithFlags(&s_fork, cudaEventDisableTiming);
        cudaEventCreateWithFlags(&s_join, cudaEventDisableTiming);
        cudaEventCreateWithFlags(&s_build, cudaEventDisableTiming);
    }

    // fork
    cudaEventRecord(s_fork, (cudaStream_t)0);
    cudaStreamWaitEvent(s_side, s_fork, 0);

    // -- branch B (side): grid build (coords only), then qkv GEMM
    grid_build_kernel<<<BB, 512, 0, s_side>>>(coords);
    cudaEventRecord(s_build, s_side);
    gemm128_kernel<false><<<dim3(QKVN / 64, ROWS / 128), 256, 0, s_side>>>(
        x, qkv_w, qkv_b, qkv_p, QKVN, CC);

    // -- branch A (main): offset net
    gemm128_kernel<true><<<dim3(2, ROWS / 128), 256>>>(
        x, off_w1, off_b1, h1_p, CH, CC);
    gemm_bias_kernel<false><<<dim3(1, ROWS / 64), 256>>>(
        h1_p, off_w2, off_b2, off_p, ROWS, 3 * KK, CH);

    // NN needs offsets (branch A) + grid (branch B build)
    cudaStreamWaitEvent((cudaStream_t)0, s_build, 0);
    nn_query_kernel<<<dim3(64, BB), 512>>>(coords);

    // join: attn needs qkv (branch B) and NN (branch A)
    cudaEventRecord(s_join, s_side);
    cudaStreamWaitEvent((cudaStream_t)0, s_join, 0);

    // attention + positional bias
    attn_kernel<<<ROWS / 8, 256>>>(pos_w1, pos_b1, pos_w2, pos_b2);

    // out = attn_out @ proj_w + proj_b   [8192,192]
    gemm128_kernel<false><<<dim3(CC / 64, ROWS / 128), 256>>>(
        att_p, proj_w, proj_b, out, CC, CC);
}

// round 16
// speedup vs baseline: 1.6368x; 1.6368x over previous
#include <cuda_runtime.h>
#include <cuda_bf16.h>
#include <math.h>

// Problem constants
#define BB 4
#define NN 2048
#define CC 192
#define HH 6
#define DD 32
#define KK 16
#define CH 96          // offset hidden
#define PH 48          // pos hidden
#define ROWS (BB*NN)   // 8192
#define QKVN (3*CC)    // 576

// ---------------- scratch (static device globals; no allocation) ----------------
__device__ float  g_qkv[ROWS * QKVN];      // 18.9 MB
__device__ float  g_h1[ROWS * CH];         // 3.1 MB
__device__ float  g_off[ROWS * 3 * KK];    // 1.57 MB  [B,N,K,3]
__device__ int    g_nn[ROWS * KK];         // nearest indices
__device__ float  g_attn_out[ROWS * CC];   // 6.3 MB
__device__ float  g_bias[ROWS * KK * HH];  // 3.1 MB  pos-MLP bias [row][k][h]

// ---------------- XLA/Eigen-replica erf (f32 rational, clamp [-4,4]) ------------
// Offset path only — feeds NN, must stay bit-exact.
__device__ __forceinline__ float xla_erf(float x) {
    x = fmaxf(fminf(x, 4.0f), -4.0f);
    float x2 = __fmul_rn(x, x);
    float p = -2.72614225801306e-10f;
    p = __fmaf_rn(p, x2,  2.77068142495902e-08f);
    p = __fmaf_rn(p, x2, -2.10102402082508e-06f);
    p = __fmaf_rn(p, x2, -5.69250639462346e-05f);
    p = __fmaf_rn(p, x2, -7.34990630326855e-04f);
    p = __fmaf_rn(p, x2, -2.95459980854025e-03f);
    p = __fmaf_rn(p, x2, -1.60960333262415e-02f);
    p = __fmul_rn(x, p);
    float q = -1.45660718464996e-05f;
    q = __fmaf_rn(q, x2, -2.13374055278905e-04f);
    q = __fmaf_rn(q, x2, -1.68282697438203e-03f);
    q = __fmaf_rn(q, x2, -7.37332916720468e-03f);
    q = __fmaf_rn(q, x2, -1.42647390514189e-02f);
    return __fdiv_rn(p, q);
}

// jax.nn.gelu(approximate=False) bit-exact replica (offset path only)
__device__ __forceinline__ float gelu_ref(float x) {
    float t = __fdiv_rn(x, 1.41421356237309504880f);
    float e = xla_erf(t);
    return __fmul_rn(__fmul_rn(x, __fadd_rn(e, 1.0f)), 0.5f);
}

// Fast gelu for the pos-bias MLP (softmax path — 1e-3 budget)
__device__ __forceinline__ float gelu_fast(float x) {
    return 0.5f * x * (1.0f + erff(x * 0.70710678118654752440f));
}

// ---------------- GEMM v2: BM=128, BN=64, BK=16, 256 thr, 8x4 microtile ---------
template<bool GELU>
__global__ void gemm128_kernel(const float* __restrict__ A, const float* __restrict__ B,
                               const float* __restrict__ bias, float* __restrict__ C,
                               int N, int K) {
    __shared__ float As[16][132];
    __shared__ float Bs[16][64];
    const int tid = threadIdx.x;
    const int tx = tid & 15;
    const int ty = tid >> 4;
    const int rowBase = blockIdx.y * 128;
    const int colBase = blockIdx.x * 64;

    float acc[8][4];
#pragma unroll
    for (int i = 0; i < 8; i++)
#pragma unroll
        for (int j = 0; j < 4; j++) acc[i][j] = 0.f;

    for (int k0 = 0; k0 < K; k0 += 16) {
#pragma unroll
        for (int t = 0; t < 8; t++) {
            int idx = tid + t * 256;
            int r = idx >> 4, c = idx & 15;
            As[c][r] = A[(rowBase + r) * K + k0 + c];
        }
#pragma unroll
        for (int t = 0; t < 4; t++) {
            int idx = tid + t * 256;
            int r = idx >> 6, c = idx & 63;
            int col = colBase + c;
            Bs[r][c] = (col < N) ? B[(k0 + r) * N + col] : 0.f;
        }
        __syncthreads();
#pragma unroll
        for (int k = 0; k < 16; k++) {
            float4 a0 = *(const float4*)&As[k][ty * 8];
            float4 a1 = *(const float4*)&As[k][ty * 8 + 4];
            float4 bv4 = *(const float4*)&Bs[k][tx * 4];
            float av[8] = {a0.x, a0.y, a0.z, a0.w, a1.x, a1.y, a1.z, a1.w};
            float bv[4] = {bv4.x, bv4.y, bv4.z, bv4.w};
#pragma unroll
            for (int i = 0; i < 8; i++)
#pragma unroll
                for (int j = 0; j < 4; j++)
                    acc[i][j] = __fmaf_rn(av[i], bv[j], acc[i][j]);
        }
        __syncthreads();
    }
#pragma unroll
    for (int i = 0; i < 8; i++) {
        int row = rowBase + ty * 8 + i;
#pragma unroll
        for (int j = 0; j < 4; j++) {
            int col = colBase + tx * 4 + j;
            if (col < N) {
                float v = __fadd_rn(acc[i][j], bias[col]);
                if (GELU) v = gelu_ref(v);
                C[row * N + col] = v;
            }
        }
    }
}

// ---------------- GEMM 64x64 (N=48 offset GEMM) --------------------------------
template<bool GELU>
__global__ void gemm_bias_kernel(const float* __restrict__ A, const float* __restrict__ B,
                                 const float* __restrict__ bias, float* __restrict__ C,
                                 int M, int N, int K) {
    __shared__ float As[16][68];
    __shared__ float Bs[16][64];
    const int tid = threadIdx.x;
    const int tx = tid & 15;
    const int ty = tid >> 4;
    const int rowBase = blockIdx.y * 64;
    const int colBase = blockIdx.x * 64;

    float acc[4][4];
#pragma unroll
    for (int i = 0; i < 4; i++)
#pragma unroll
        for (int j = 0; j < 4; j++) acc[i][j] = 0.f;

    for (int k0 = 0; k0 < K; k0 += 16) {
#pragma unroll
        for (int t = 0; t < 4; t++) {
            int idx = tid + t * 256;
            int r = idx >> 4, c = idx & 15;
            As[c][r] = A[(rowBase + r) * K + k0 + c];
        }
#pragma unroll
        for (int t = 0; t < 4; t++) {
            int idx = tid + t * 256;
            int r = idx >> 6, c = idx & 63;
            int col = colBase + c;
            Bs[r][c] = (col < N) ? B[(k0 + r) * N + col] : 0.f;
        }
        __syncthreads();
#pragma unroll
        for (int k = 0; k < 16; k++) {
            float4 av4 = *(const float4*)&As[k][ty * 4];
            float4 bv4 = *(const float4*)&Bs[k][tx * 4];
            float av[4] = {av4.x, av4.y, av4.z, av4.w};
            float bv[4] = {bv4.x, bv4.y, bv4.z, bv4.w};
#pragma unroll
            for (int i = 0; i < 4; i++)
#pragma unroll
                for (int j = 0; j < 4; j++)
                    acc[i][j] = __fmaf_rn(av[i], bv[j], acc[i][j]);
        }
        __syncthreads();
    }
#pragma unroll
    for (int i = 0; i < 4; i++) {
        int row = rowBase + ty * 4 + i;
#pragma unroll
        for (int j = 0; j < 4; j++) {
            int col = colBase + tx * 4 + j;
            if (col < N) {
                float v = __fadd_rn(acc[i][j], bias[col]);
                if (GELU) v = gelu_ref(v);
                C[row * N + col] = v;
            }
        }
    }
}

// ---------------- nearest neighbor (R13 brute force — proven 80us) --------------
// Reference-exact d2 rounding (DO NOT change the arithmetic).
template<int NQ>
__device__ __forceinline__ void nn_scan(const float4* __restrict__ sk,
                                        const float* __restrict__ coords,
                                        int b, int base, int lane) {
    float sx[NQ], sy[NQ], sz[NQ], S[NQ], best[NQ];
    int bi[NQ], qidx[NQ];
#pragma unroll
    for (int q = 0; q < NQ; q++) {
        int qi = (base + q) * 32 + lane;          // 0..32767 within batch
        qidx[q] = qi;
        int n = qi >> 4, k = qi & 15;
        const float* cr = coords + (b * NN + n) * 3;
        const float* of = g_off + (b * NN + n) * 48 + k * 3;
        sx[q] = __fadd_rn(cr[0], __fmul_rn(of[0], 10.0f));
        sy[q] = __fadd_rn(cr[1], __fmul_rn(of[1], 10.0f));
        sz[q] = __fadd_rn(cr[2], __fmul_rn(of[2], 10.0f));
        S[q]  = __fadd_rn(__fadd_rn(__fmul_rn(sx[q], sx[q]), __fmul_rn(sy[q], sy[q])),
                          __fmul_rn(sz[q], sz[q]));
        best[q] = 3.4e38f;
        bi[q] = 0;
    }
#pragma unroll 8
    for (int i = 0; i < NN; i++) {
        float4 kk = sk[i];
#pragma unroll
        for (int q = 0; q < NQ; q++) {
            float dot = __fmaf_rn(sz[q], kk.z,
                        __fmaf_rn(sy[q], kk.y, __fmul_rn(sx[q], kk.x)));
            float d = __fadd_rn(__fmaf_rn(dot, -2.0f, S[q]), kk.w);
            if (d < best[q]) { best[q] = d; bi[q] = i; }
        }
    }
#pragma unroll
    for (int q = 0; q < NQ; q++)
        g_nn[b * (NN * KK) + qidx[q]] = bi[q];
}

__global__ void __launch_bounds__(512, 1) nn_kernel(const float* __restrict__ coords) {
    __shared__ float4 sk[NN];   // 32 KB
    const int b = blockIdx.y;
    for (int i = threadIdx.x; i < NN; i += 512) {
        const float* c = coords + (b * NN + i) * 3;
        float x = c[0], y = c[1], z = c[2];
        float s = __fadd_rn(__fadd_rn(__fmul_rn(x, x), __fmul_rn(y, y)), __fmul_rn(z, z));
        sk[i] = make_float4(x, y, z, s);
    }
    __syncthreads();

    const int w = threadIdx.x >> 5, lane = threadIdx.x & 31;
    const int wib = blockIdx.x * 16 + w;                // 0..607
    const int base = (wib * 1024) / 608;
    const int nq = ((wib + 1) * 1024) / 608 - base;     // 1 or 2
    if (nq == 2) nn_scan<2>(sk, coords, b, base, lane);
    else         nn_scan<1>(sk, coords, b, base, lane);
}

// ---------------- pos-MLP bias kernel: writes g_bias[row][k][h] -----------------
// Softmax path: fast math is fine (1e-3 budget).
__global__ void bias_kernel(const float* __restrict__ pos_w1, const float* __restrict__ pos_b1,
                            const float* __restrict__ pos_w2, const float* __restrict__ pos_b2) {
    __shared__ float spw1[144], spb1[48], spw2[288], spb2[8];
    __shared__ float shid[8][768];
    __shared__ float soff[8][48];

    const int tid = threadIdx.x;
    for (int i = tid; i < 144; i += 256) spw1[i] = pos_w1[i];
    for (int i = tid; i < 48;  i += 256) spb1[i] = pos_b1[i];
    for (int i = tid; i < 288; i += 256) spw2[i] = pos_w2[i];
    if (tid < 6) spb2[tid] = pos_b2[tid];
    __syncthreads();

    const int w = tid >> 5, lane = tid & 31;
    const int row = blockIdx.x * 8 + w;     // 0..8191

    for (int t = lane; t < 48; t += 32) soff[w][t] = g_off[row * 48 + t];
    __syncwarp();

#pragma unroll 4
    for (int t = 0; t < 24; t++) {
        int idx = t * 32 + lane;
        int k = idx / 48, j = idx - k * 48;
        float o0 = soff[w][k * 3 + 0];
        float o1 = soff[w][k * 3 + 1];
        float o2 = soff[w][k * 3 + 2];
        float hv = fmaf(o0, spw1[j], spb1[j]);
        hv = fmaf(o1, spw1[48 + j], hv);
        hv = fmaf(o2, spw1[96 + j], hv);
        shid[w][k * 48 + j] = gelu_fast(hv);
    }
    __syncwarp();

#pragma unroll
    for (int t = 0; t < 3; t++) {
        int idx = t * 32 + lane;
        int k = idx / 6, h = idx - k * 6;
        float s = spb2[h];
#pragma unroll 8
        for (int j = 0; j < 48; j++)
            s = fmaf(shid[w][k * 48 + j], spw2[j * 6 + h], s);
        g_bias[row * 96 + idx] = s;
    }
}

// ---------------- attention core: one warp per (row, head) ----------------------
// 192 threads = 6 warps = 6 heads of one row. lane=(half=lane>>4, k=lane&15):
// 16-elem partial dot per lane + one shfl_xor(16) completes all 16 QK dots.
// 49152 warps total -> deep MLP to hide the scattered L2 gathers.
__global__ void __launch_bounds__(192) attn_core_kernel() {
    __shared__ int   snn[16];
    __shared__ float sa[6][16];

    const int row = blockIdx.x;             // 0..8191
    const int b = row >> 11;
    const int tid = threadIdx.x;
    const int h = tid / 32, lane = tid & 31;
    const int myk = lane & 15, half = lane >> 4;
    const unsigned FULL = 0xffffffffu;

    if (tid < 16) snn[tid] = g_nn[row * 16 + tid];
    __syncthreads();

    const int hoff = h * DD;
    const int krow = (b * NN + snn[myk]) * QKVN;
    const float* qrow = g_qkv + (size_t)row * QKVN;

    // ---- QK^T ----
    const float4* qp = (const float4*)(qrow + hoff + half * 16);
    const float4* kp = (const float4*)(g_qkv + krow + CC + hoff + half * 16);
    float4 q0 = qp[0], q1 = qp[1], q2 = qp[2], q3 = qp[3];
    float4 k0 = kp[0], k1 = kp[1], k2 = kp[2], k3 = kp[3];
    float p = q0.x * k0.x;
    p = fmaf(q0.y, k0.y, p); p = fmaf(q0.z, k0.z, p); p = fmaf(q0.w, k0.w, p);
    p = fmaf(q1.x, k1.x, p); p = fmaf(q1.y, k1.y, p); p = fmaf(q1.z, k1.z, p); p = fmaf(q1.w, k1.w, p);
    p = fmaf(q2.x, k2.x, p); p = fmaf(q2.y, k2.y, p); p = fmaf(q2.z, k2.z, p); p = fmaf(q2.w, k2.w, p);
    p = fmaf(q3.x, k3.x, p); p = fmaf(q3.y, k3.y, p); p = fmaf(q3.z, k3.z, p); p = fmaf(q3.w, k3.w, p);
    float dot = p + __shfl_xor_sync(FULL, p, 16);

    float logit = fmaf(dot, 0.17677669529663687f, g_bias[row * 96 + myk * 6 + h]);
    // softmax over 16 (duplicated across halves)
    float m = logit;
    m = fmaxf(m, __shfl_xor_sync(FULL, m, 8));
    m = fmaxf(m, __shfl_xor_sync(FULL, m, 4));
    m = fmaxf(m, __shfl_xor_sync(FULL, m, 2));
    m = fmaxf(m, __shfl_xor_sync(FULL, m, 1));
    float e = __expf(logit - m);
    float s = e;
    s += __shfl_xor_sync(FULL, s, 8);
    s += __shfl_xor_sync(FULL, s, 4);
    s += __shfl_xor_sync(FULL, s, 2);
    s += __shfl_xor_sync(FULL, s, 1);
    float a = __fdividef(e, s);
    if (lane < 16) sa[h][lane] = a;
    __syncwarp();

    // ---- AV: lane = d (0..31) ----
    float acc = 0.f;
#pragma unroll
    for (int k4 = 0; k4 < 4; k4++) {
        float4 a4 = *(const float4*)&sa[h][k4 * 4];
        int n0 = snn[k4 * 4 + 0], n1 = snn[k4 * 4 + 1];
        int n2 = snn[k4 * 4 + 2], n3 = snn[k4 * 4 + 3];
        acc = fmaf(a4.x, g_qkv[(size_t)(b * NN + n0) * QKVN + 2 * CC + hoff + lane], acc);
        acc = fmaf(a4.y, g_qkv[(size_t)(b * NN + n1) * QKVN + 2 * CC + hoff + lane], acc);
        acc = fmaf(a4.z, g_qkv[(size_t)(b * NN + n2) * QKVN + 2 * CC + hoff + lane], acc);
        acc = fmaf(a4.w, g_qkv[(size_t)(b * NN + n3) * QKVN + 2 * CC + hoff + lane], acc);
    }
    g_attn_out[(size_t)row * CC + hoff + lane] = acc;
}

// ---------------- launch: main {h1→off→NN→attn→proj} ∥ side {qkv→bias} ---------
extern "C" void kernel_launch(void* const* d_in, const int* in_sizes, int n_in,
                              void* d_out, int out_size) {
    const float* coords  = (const float*)d_in[0];
    const float* x       = (const float*)d_in[1];
    const float* qkv_w   = (const float*)d_in[2];
    const float* qkv_b   = (const float*)d_in[3];
    const float* proj_w  = (const float*)d_in[4];
    const float* proj_b  = (const float*)d_in[5];
    const float* off_w1  = (const float*)d_in[6];
    const float* off_b1  = (const float*)d_in[7];
    const float* off_w2  = (const float*)d_in[8];
    const float* off_b2  = (const float*)d_in[9];
    const float* pos_w1  = (const float*)d_in[10];
    const float* pos_b1  = (const float*)d_in[11];
    const float* pos_w2  = (const float*)d_in[12];
    const float* pos_b2  = (const float*)d_in[13];
    float* out = (float*)d_out;

    float *qkv_p, *h1_p, *off_p, *att_p;
    cudaGetSymbolAddress((void**)&qkv_p, g_qkv);
    cudaGetSymbolAddress((void**)&h1_p,  g_h1);
    cudaGetSymbolAddress((void**)&off_p, g_off);
    cudaGetSymbolAddress((void**)&att_p, g_attn_out);

    // Lazily-created side stream + events (host-side objects only).
    static cudaStream_t s_side = nullptr;
    static cudaEvent_t  s_fork = nullptr, s_join = nullptr, s_off = nullptr;
    if (s_side == nullptr) {
        cudaStreamCreateWithFlags(&s_side, cudaStreamNonBlocking);
        cudaEventCreateWithFlags(&s_fork, cudaEventDisableTiming);
        cudaEventCreateWithFlags(&s_join, cudaEventDisableTiming);
        cudaEventCreateWithFlags(&s_off, cudaEventDisableTiming);
    }

    // fork
    cudaEventRecord(s_fork, (cudaStream_t)0);
    cudaStreamWaitEvent(s_side, s_fork, 0);

    // -- branch A (main): offset net
    gemm128_kernel<true><<<dim3(2, ROWS / 128), 256>>>(
        x, off_w1, off_b1, h1_p, CH, CC);
    gemm_bias_kernel<false><<<dim3(1, ROWS / 64), 256>>>(
        h1_p, off_w2, off_b2, off_p, ROWS, 3 * KK, CH);
    cudaEventRecord(s_off, (cudaStream_t)0);

    // -- branch B (side): qkv GEMM, then pos-MLP bias (needs g_off)
    gemm128_kernel<false><<<dim3(QKVN / 64, ROWS / 128), 256, 0, s_side>>>(
        x, qkv_w, qkv_b, qkv_p, QKVN, CC);
    cudaStreamWaitEvent(s_side, s_off, 0);
    bias_kernel<<<ROWS / 8, 256, 0, s_side>>>(pos_w1, pos_b1, pos_w2, pos_b2);

    // -- branch A continues: NN brute force
    nn_kernel<<<dim3(38, BB), 512>>>(coords);

    // join: attn needs qkv+bias (side) and NN (main)
    cudaEventRecord(s_join, s_side);
    cudaStreamWaitEvent((cudaStream_t)0, s_join, 0);

    // attention core (one warp per row-head)
    attn_core_kernel<<<ROWS, 192>>>();

    // out = attn_out @ proj_w + proj_b   [8192,192]
    gemm128_kernel<false><<<dim3(CC / 64, ROWS / 128), 256>>>(
        att_p, proj_w, proj_b, out, CC, CC);
}

// round 17
// speedup vs baseline: 1.9720x; 1.2048x over previous
#include <cuda_runtime.h>
#include <cuda_bf16.h>
#include <math.h>

// Problem constants
#define BB 4
#define NN 2048
#define CC 192
#define HH 6
#define DD 32
#define KK 16
#define CH 96          // offset hidden
#define PH 48          // pos hidden
#define ROWS (BB*NN)   // 8192
#define QKVN (3*CC)    // 576

// ---------------- scratch (static device globals; no allocation) ----------------
__device__ float  g_qkv[ROWS * QKVN];      // 18.9 MB
__device__ float  g_h1[ROWS * CH];         // 3.1 MB
__device__ float  g_off[ROWS * 3 * KK];    // 1.57 MB  [B,N,K,3]
__device__ int    g_nn[ROWS * KK];         // nearest indices
__device__ float  g_attn_out[ROWS * CC];   // 6.3 MB

// ---------------- XLA/Eigen-replica erf (f32 rational, clamp [-4,4]) ------------
__device__ __forceinline__ float xla_erf(float x) {
    x = fmaxf(fminf(x, 4.0f), -4.0f);
    float x2 = __fmul_rn(x, x);
    float p = -2.72614225801306e-10f;
    p = __fmaf_rn(p, x2,  2.77068142495902e-08f);
    p = __fmaf_rn(p, x2, -2.10102402082508e-06f);
    p = __fmaf_rn(p, x2, -5.69250639462346e-05f);
    p = __fmaf_rn(p, x2, -7.34990630326855e-04f);
    p = __fmaf_rn(p, x2, -2.95459980854025e-03f);
    p = __fmaf_rn(p, x2, -1.60960333262415e-02f);
    p = __fmul_rn(x, p);
    float q = -1.45660718464996e-05f;
    q = __fmaf_rn(q, x2, -2.13374055278905e-04f);
    q = __fmaf_rn(q, x2, -1.68282697438203e-03f);
    q = __fmaf_rn(q, x2, -7.37332916720468e-03f);
    q = __fmaf_rn(q, x2, -1.42647390514189e-02f);
    return __fdiv_rn(p, q);
}

// jax.nn.gelu(approximate=False) bit-exact replica
__device__ __forceinline__ float gelu_ref(float x) {
    float t = __fdiv_rn(x, 1.41421356237309504880f);
    float e = xla_erf(t);
    return __fmul_rn(__fmul_rn(x, __fadd_rn(e, 1.0f)), 0.5f);
}

// ---------------- GEMM 128x64, double-buffered (reg prefetch, 1 sync/iter) ------
// Per-output accumulation: sequential fma chain over k ascending, init 0, bias
// added after — arithmetic identical to previous rounds (scheduling only).
template<bool GELU>
__global__ void __launch_bounds__(256) gemm128_kernel(
        const float* __restrict__ A, const float* __restrict__ B,
        const float* __restrict__ bias, float* __restrict__ C,
        int N, int K) {
    __shared__ float As[2][16][132];
    __shared__ float Bs[2][16][64];
    const int tid = threadIdx.x;
    const int tx = tid & 15;
    const int ty = tid >> 4;
    const int rowBase = blockIdx.y * 128;
    const int colBase = blockIdx.x * 64;
    const int T = K / 16;

    float acc[8][4];
#pragma unroll
    for (int i = 0; i < 8; i++)
#pragma unroll
        for (int j = 0; j < 4; j++) acc[i][j] = 0.f;

    // tile 0 -> smem[0]
#pragma unroll
    for (int t = 0; t < 8; t++) {
        int idx = tid + t * 256;
        int r = idx >> 4, c = idx & 15;
        As[0][c][r] = A[(rowBase + r) * K + c];
    }
#pragma unroll
    for (int t = 0; t < 4; t++) {
        int idx = tid + t * 256;
        int r = idx >> 6, c = idx & 63;
        int col = colBase + c;
        Bs[0][r][c] = (col < N) ? B[r * N + col] : 0.f;
    }
    __syncthreads();

    float ra[8], rb[4];
    for (int kt = 0; kt < T; kt++) {
        const int cur = kt & 1;
        const bool more = (kt + 1 < T);
        if (more) {
            int k0 = (kt + 1) * 16;
#pragma unroll
            for (int t = 0; t < 8; t++) {
                int idx = tid + t * 256;
                int r = idx >> 4, c = idx & 15;
                ra[t] = A[(rowBase + r) * K + k0 + c];
            }
#pragma unroll
            for (int t = 0; t < 4; t++) {
                int idx = tid + t * 256;
                int r = idx >> 6, c = idx & 63;
                int col = colBase + c;
                rb[t] = (col < N) ? B[(k0 + r) * N + col] : 0.f;
            }
        }
#pragma unroll
        for (int k = 0; k < 16; k++) {
            float4 a0 = *(const float4*)&As[cur][k][ty * 8];
            float4 a1 = *(const float4*)&As[cur][k][ty * 8 + 4];
            float4 bv4 = *(const float4*)&Bs[cur][k][tx * 4];
            float av[8] = {a0.x, a0.y, a0.z, a0.w, a1.x, a1.y, a1.z, a1.w};
            float bv[4] = {bv4.x, bv4.y, bv4.z, bv4.w};
#pragma unroll
            for (int i = 0; i < 8; i++)
#pragma unroll
                for (int j = 0; j < 4; j++)
                    acc[i][j] = __fmaf_rn(av[i], bv[j], acc[i][j]);
        }
        if (more) {
            const int nxt = cur ^ 1;
#pragma unroll
            for (int t = 0; t < 8; t++) {
                int idx = tid + t * 256;
                int r = idx >> 4, c = idx & 15;
                As[nxt][c][r] = ra[t];
            }
#pragma unroll
            for (int t = 0; t < 4; t++) {
                int idx = tid + t * 256;
                int r = idx >> 6, c = idx & 63;
                Bs[nxt][r][c] = rb[t];
            }
            __syncthreads();
        }
    }
#pragma unroll
    for (int i = 0; i < 8; i++) {
        int row = rowBase + ty * 8 + i;
#pragma unroll
        for (int j = 0; j < 4; j++) {
            int col = colBase + tx * 4 + j;
            if (col < N) {
                float v = __fadd_rn(acc[i][j], bias[col]);
                if (GELU) v = gelu_ref(v);
                C[row * N + col] = v;
            }
        }
    }
}

// ---------------- GEMM 64x64, double-buffered ----------------------------------
template<bool GELU>
__global__ void __launch_bounds__(256) gemm_bias_kernel(
        const float* __restrict__ A, const float* __restrict__ B,
        const float* __restrict__ bias, float* __restrict__ C,
        int M, int N, int K) {
    __shared__ float As[2][16][68];
    __shared__ float Bs[2][16][64];
    const int tid = threadIdx.x;
    const int tx = tid & 15;
    const int ty = tid >> 4;
    const int rowBase = blockIdx.y * 64;
    const int colBase = blockIdx.x * 64;
    const int T = K / 16;

    float acc[4][4];
#pragma unroll
    for (int i = 0; i < 4; i++)
#pragma unroll
        for (int j = 0; j < 4; j++) acc[i][j] = 0.f;

#pragma unroll
    for (int t = 0; t < 4; t++) {
        int idx = tid + t * 256;
        int r = idx >> 4, c = idx & 15;
        As[0][c][r] = A[(rowBase + r) * K + c];
    }
#pragma unroll
    for (int t = 0; t < 4; t++) {
        int idx = tid + t * 256;
        int r = idx >> 6, c = idx & 63;
        int col = colBase + c;
        Bs[0][r][c] = (col < N) ? B[r * N + col] : 0.f;
    }
    __syncthreads();

    float ra[4], rb[4];
    for (int kt = 0; kt < T; kt++) {
        const int cur = kt & 1;
        const bool more = (kt + 1 < T);
        if (more) {
            int k0 = (kt + 1) * 16;
#pragma unroll
            for (int t = 0; t < 4; t++) {
                int idx = tid + t * 256;
                int r = idx >> 4, c = idx & 15;
                ra[t] = A[(rowBase + r) * K + k0 + c];
            }
#pragma unroll
            for (int t = 0; t < 4; t++) {
                int idx = tid + t * 256;
                int r = idx >> 6, c = idx & 63;
                int col = colBase + c;
                rb[t] = (col < N) ? B[(k0 + r) * N + col] : 0.f;
            }
        }
#pragma unroll
        for (int k = 0; k < 16; k++) {
            float4 av4 = *(const float4*)&As[cur][k][ty * 4];
            float4 bv4 = *(const float4*)&Bs[cur][k][tx * 4];
            float av[4] = {av4.x, av4.y, av4.z, av4.w};
            float bv[4] = {bv4.x, bv4.y, bv4.z, bv4.w};
#pragma unroll
            for (int i = 0; i < 4; i++)
#pragma unroll
                for (int j = 0; j < 4; j++)
                    acc[i][j] = __fmaf_rn(av[i], bv[j], acc[i][j]);
        }
        if (more) {
            const int nxt = cur ^ 1;
#pragma unroll
            for (int t = 0; t < 4; t++) {
                int idx = tid + t * 256;
                int r = idx >> 4, c = idx & 15;
                As[nxt][c][r] = ra[t];
            }
#pragma unroll
            for (int t = 0; t < 4; t++) {
                int idx = tid + t * 256;
                int r = idx >> 6, c = idx & 63;
                Bs[nxt][r][c] = rb[t];
            }
            __syncthreads();
        }
    }
#pragma unroll
    for (int i = 0; i < 4; i++) {
        int row = rowBase + ty * 4 + i;
#pragma unroll
        for (int j = 0; j < 4; j++) {
            int col = colBase + tx * 4 + j;
            if (col < N) {
                float v = __fadd_rn(acc[i][j], bias[col]);
                if (GELU) v = gelu_ref(v);
                C[row * N + col] = v;
            }
        }
    }
}

// ---------------- nearest neighbor (R13 — proven 80us) --------------------------
// Reference-exact d2 rounding (DO NOT change the arithmetic).
template<int NQ>
__device__ __forceinline__ void nn_scan(const float4* __restrict__ sk,
                                        const float* __restrict__ coords,
                                        int b, int base, int lane) {
    float sx[NQ], sy[NQ], sz[NQ], S[NQ], best[NQ];
    int bi[NQ], qidx[NQ];
#pragma unroll
    for (int q = 0; q < NQ; q++) {
        int qi = (base + q) * 32 + lane;          // 0..32767 within batch
        qidx[q] = qi;
        int n = qi >> 4, k = qi & 15;
        const float* cr = coords + (b * NN + n) * 3;
        const float* of = g_off + (b * NN + n) * 48 + k * 3;
        sx[q] = __fadd_rn(cr[0], __fmul_rn(of[0], 10.0f));
        sy[q] = __fadd_rn(cr[1], __fmul_rn(of[1], 10.0f));
        sz[q] = __fadd_rn(cr[2], __fmul_rn(of[2], 10.0f));
        S[q]  = __fadd_rn(__fadd_rn(__fmul_rn(sx[q], sx[q]), __fmul_rn(sy[q], sy[q])),
                          __fmul_rn(sz[q], sz[q]));
        best[q] = 3.4e38f;
        bi[q] = 0;
    }
#pragma unroll 8
    for (int i = 0; i < NN; i++) {
        float4 kk = sk[i];
#pragma unroll
        for (int q = 0; q < NQ; q++) {
            float dot = __fmaf_rn(sz[q], kk.z,
                        __fmaf_rn(sy[q], kk.y, __fmul_rn(sx[q], kk.x)));
            float d = __fadd_rn(__fmaf_rn(dot, -2.0f, S[q]), kk.w);
            if (d < best[q]) { best[q] = d; bi[q] = i; }
        }
    }
#pragma unroll
    for (int q = 0; q < NQ; q++)
        g_nn[b * (NN * KK) + qidx[q]] = bi[q];
}

__global__ void __launch_bounds__(512, 1) nn_kernel(const float* __restrict__ coords) {
    __shared__ float4 sk[NN];   // 32 KB
    const int b = blockIdx.y;
    for (int i = threadIdx.x; i < NN; i += 512) {
        const float* c = coords + (b * NN + i) * 3;
        float x = c[0], y = c[1], z = c[2];
        float s = __fadd_rn(__fadd_rn(__fmul_rn(x, x), __fmul_rn(y, y)), __fmul_rn(z, z));
        sk[i] = make_float4(x, y, z, s);
    }
    __syncthreads();

    const int w = threadIdx.x >> 5, lane = threadIdx.x & 31;
    const int wib = blockIdx.x * 16 + w;                // 0..607
    const int base = (wib * 1024) / 608;
    const int nq = ((wib + 1) * 1024) / 608 - base;     // 1 or 2
    if (nq == 2) nn_scan<2>(sk, coords, b, base, lane);
    else         nn_scan<1>(sk, coords, b, base, lane);
}

// ---------------- attention + pos-bias MLP (R13 version — proven) ---------------
__global__ void attn_kernel(const float* __restrict__ pos_w1, const float* __restrict__ pos_b1,
                            const float* __restrict__ pos_w2, const float* __restrict__ pos_b2) {
    __shared__ float spw1[144], spb1[48], spw2[288], spb2[8];
    __shared__ float shid[8][768];
    __shared__ float sbias[8][96];
    __shared__ float soff[8][48];
    __shared__ int   snn[8][16];

    const int tid = threadIdx.x;
    for (int i = tid; i < 144; i += 256) spw1[i] = pos_w1[i];
    for (int i = tid; i < 48;  i += 256) spb1[i] = pos_b1[i];
    for (int i = tid; i < 288; i += 256) spw2[i] = pos_w2[i];
    if (tid < 6) spb2[tid] = pos_b2[tid];
    __syncthreads();

    const int w = tid >> 5, lane = tid & 31;
    const int gw = blockIdx.x * 8 + w;      // 0..8191
    const int b = gw >> 11, n = gw & 2047;
    const int row = b * NN + n;

    for (int t = lane; t < 48; t += 32) soff[w][t] = g_off[row * 48 + t];
    if (lane < 16) snn[w][lane] = g_nn[row * 16 + lane];
    __syncwarp();

#pragma unroll 4
    for (int t = 0; t < 24; t++) {
        int idx = t * 32 + lane;
        int k = idx / 48, j = idx - k * 48;
        float o0 = soff[w][k * 3 + 0];
        float o1 = soff[w][k * 3 + 1];
        float o2 = soff[w][k * 3 + 2];
        float hv = __fmaf_rn(o0, spw1[j], spb1[j]);
        hv = __fmaf_rn(o1, spw1[48 + j], hv);
        hv = __fmaf_rn(o2, spw1[96 + j], hv);
        shid[w][k * 48 + j] = gelu_ref(hv);
    }
    __syncwarp();

#pragma unroll
    for (int t = 0; t < 3; t++) {
        int idx = t * 32 + lane;
        int k = idx / 6, h = idx - k * 6;
        float s = spb2[h];
#pragma unroll 8
        for (int j = 0; j < 48; j++)
            s = __fmaf_rn(shid[w][k * 48 + j], spw2[j * 6 + h], s);
        sbias[w][idx] = s;
    }
    __syncwarp();

    const float* qrow = g_qkv + (size_t)row * QKVN;
    float* orow = g_attn_out + (size_t)row * CC;
    const unsigned FULL = 0xffffffffu;

    for (int h = 0; h < HH; h++) {
        float qd = qrow[h * DD + lane];
        float lk = 0.f;
#pragma unroll
        for (int k = 0; k < KK; k++) {
            int nk = snn[w][k];
            float kv = g_qkv[(size_t)(b * NN + nk) * QKVN + CC + h * DD + lane];
            float p = qd * kv;
            p += __shfl_xor_sync(FULL, p, 16);
            p += __shfl_xor_sync(FULL, p, 8);
            p += __shfl_xor_sync(FULL, p, 4);
            p += __shfl_xor_sync(FULL, p, 2);
            p += __shfl_xor_sync(FULL, p, 1);
            if (lane == k) lk = p;
        }
        float logit = (lane < KK)
                      ? (lk * 0.17677669529663687f + sbias[w][lane * 6 + h])
                      : -1e30f;
        float m = logit;
        m = fmaxf(m, __shfl_xor_sync(FULL, m, 8));
        m = fmaxf(m, __shfl_xor_sync(FULL, m, 4));
        m = fmaxf(m, __shfl_xor_sync(FULL, m, 2));
        m = fmaxf(m, __shfl_xor_sync(FULL, m, 1));
        float e = (lane < KK) ? expf(logit - m) : 0.f;
        float s = e;
        s += __shfl_xor_sync(FULL, s, 8);
        s += __shfl_xor_sync(FULL, s, 4);
        s += __shfl_xor_sync(FULL, s, 2);
        s += __shfl_xor_sync(FULL, s, 1);
        float a = e / s;
        float od = 0.f;
#pragma unroll
        for (int k = 0; k < KK; k++) {
            float ak = __shfl_sync(FULL, a, k);
            int nk = snn[w][k];
            float vv = g_qkv[(size_t)(b * NN + nk) * QKVN + 2 * CC + h * DD + lane];
            od = __fmaf_rn(ak, vv, od);
        }
        orow[h * DD + lane] = od;
    }
}

// ---------------- launch (forked capture: qkv ∥ {h1→off→NN}) -------------------
extern "C" void kernel_launch(void* const* d_in, const int* in_sizes, int n_in,
                              void* d_out, int out_size) {
    const float* coords  = (const float*)d_in[0];
    const float* x       = (const float*)d_in[1];
    const float* qkv_w   = (const float*)d_in[2];
    const float* qkv_b   = (const float*)d_in[3];
    const float* proj_w  = (const float*)d_in[4];
    const float* proj_b  = (const float*)d_in[5];
    const float* off_w1  = (const float*)d_in[6];
    const float* off_b1  = (const float*)d_in[7];
    const float* off_w2  = (const float*)d_in[8];
    const float* off_b2  = (const float*)d_in[9];
    const float* pos_w1  = (const float*)d_in[10];
    const float* pos_b1  = (const float*)d_in[11];
    const float* pos_w2  = (const float*)d_in[12];
    const float* pos_b2  = (const float*)d_in[13];
    float* out = (float*)d_out;

    float *qkv_p, *h1_p, *off_p, *att_p;
    cudaGetSymbolAddress((void**)&qkv_p, g_qkv);
    cudaGetSymbolAddress((void**)&h1_p,  g_h1);
    cudaGetSymbolAddress((void**)&off_p, g_off);
    cudaGetSymbolAddress((void**)&att_p, g_attn_out);

    // Lazily-created side stream + fork/join events (host-side objects only).
    static cudaStream_t s_side = nullptr;
    static cudaEvent_t  s_fork = nullptr, s_join = nullptr;
    if (s_side == nullptr) {
        cudaStreamCreateWithFlags(&s_side, cudaStreamNonBlocking);
        cudaEventCreateWithFlags(&s_fork, cudaEventDisableTiming);
        cudaEventCreateWithFlags(&s_join, cudaEventDisableTiming);
    }

    // fork
    cudaEventRecord(s_fork, (cudaStream_t)0);
    cudaStreamWaitEvent(s_side, s_fork, 0);

    // -- branch B (side): qkv = x @ qkv_w + qkv_b   [8192,576]  (128x64 DB)
    gemm128_kernel<false><<<dim3(QKVN / 64, ROWS / 128), 256, 0, s_side>>>(
        x, qkv_w, qkv_b, qkv_p, QKVN, CC);

    // -- branch A (main): offset net (64x64 DB, frozen arithmetic)
    gemm_bias_kernel<true><<<dim3(2, ROWS / 64), 256>>>(
        x, off_w1, off_b1, h1_p, ROWS, CH, CC);
    gemm_bias_kernel<false><<<dim3(1, ROWS / 64), 256>>>(
        h1_p, off_w2, off_b2, off_p, ROWS, 3 * KK, CH);
    // nearest-neighbor argmin
    nn_kernel<<<dim3(38, BB), 512>>>(coords);

    // join: attn needs qkv (side) and NN (main)
    cudaEventRecord(s_join, s_side);
    cudaStreamWaitEvent((cudaStream_t)0, s_join, 0);

    // attention + positional bias (R13)
    attn_kernel<<<ROWS / 8, 256>>>(pos_w1, pos_b1, pos_w2, pos_b2);

    // out = attn_out @ proj_w + proj_b   [8192,192]  (64x64 DB, 384 blocks)
    gemm_bias_kernel<false><<<dim3(CC / 64, ROWS / 64), 256>>>(
        att_p, proj_w, proj_b, out, ROWS, CC, CC);
}